// round 3
// baseline (speedup 1.0000x reference)
#include <cuda_runtime.h>
#include <cuda_fp16.h>
#include <cstdint>
#include <cstddef>

// ---------------- problem dims ----------------
#define B_ROWS 8192
#define K_DIM  4096
#define N_DIM  4096

// ---------------- GEMM tiling -----------------
#define TM 128
#define TN 256
#define KC 64                        // fp16 per k-stage (=128B row, one SW128 atom)
#define NSTAGE 3
#define KSTAGES (K_DIM / KC)         // 64
#define A_TILE_BYTES (TM * KC * 2)   // 16384
#define B_TILE_BYTES (TN * KC * 2)   // 32768
#define STG_BYTES (2 * A_TILE_BYTES + B_TILE_BYTES)   // 65536
#define SMEM_DYN (1024 + NSTAGE * STG_BYTES)          // 197632

// ---------------- device scratch ----------------
__device__ __align__(1024) unsigned char g_w_packed[(size_t)N_DIM * K_DIM * 2]; // 32MB
__device__ __align__(1024) unsigned char g_x_hi[(size_t)B_ROWS * K_DIM * 2];    // 64MB
__device__ __align__(1024) unsigned char g_x_lo[(size_t)B_ROWS * K_DIM * 2];    // 64MB
__device__ float g_out[(size_t)B_ROWS * N_DIM];                                  // 128MB row-major
__device__ float g_fc_sf[N_DIM];
__device__ float g_bias_sf[N_DIM];
__device__ float g_b_int[N_DIM];
__device__ unsigned int g_max_bits;
__device__ float g_act_sf;

// ---------------- PTX helpers (baseline ISA only, no 'a' features) ----------------
__device__ __forceinline__ uint32_t smem_u32(const void* p) {
    return (uint32_t)__cvta_generic_to_shared(p);
}

#define MBAR_INIT(addr, cnt) \
    asm volatile("mbarrier.init.shared.b64 [%0], %1;" :: "r"(addr), "r"(cnt) : "memory")
#define MBAR_EXPECT_TX(addr, tx) \
    asm volatile("mbarrier.arrive.expect_tx.shared.b64 _, [%0], %1;" :: "r"(addr), "r"(tx) : "memory")

#define MBAR_WAIT(mbar_smem_addr, phase_parity) do { \
    uint32_t _mbar = (uint32_t)(mbar_smem_addr); \
    uint32_t _parity = (uint32_t)(phase_parity); \
    uint32_t _done; \
    asm volatile( \
        "{\n\t.reg .pred p;\n\t" \
        "mbarrier.try_wait.parity.acquire.cta.shared::cta.b64 p, [%1], %2;\n\t" \
        "selp.b32 %0, 1, 0, p;\n\t}" \
        : "=r"(_done) : "r"(_mbar), "r"(_parity) : "memory"); \
    if (!_done) { \
        asm volatile( \
            "{\n\t.reg .pred P1;\n\t" \
            "WAIT_LOOP_%=:\n\t" \
            "mbarrier.try_wait.parity.acquire.cta.shared::cta.b64 P1, [%0], %1, 0x989680;\n\t" \
            "@P1 bra.uni WAIT_DONE_%=;\n\t" \
            "bra.uni WAIT_LOOP_%=;\n\t" \
            "WAIT_DONE_%=:\n\t}" \
            :: "r"(_mbar), "r"(_parity) : "memory"); \
    } \
} while (0)

#define BULK_G2S(dst, src, nbytes, mbar) \
    asm volatile("cp.async.bulk.shared::cluster.global.mbarrier::complete_tx::bytes [%0], [%1], %2, [%3];" \
        :: "r"(dst), "l"(src), "r"(nbytes), "r"(mbar) : "memory")

__device__ __forceinline__ void ldsm_x4(uint32_t (&r)[4], uint32_t addr) {
    asm volatile("ldmatrix.sync.aligned.m8n8.x4.shared.b16 {%0,%1,%2,%3}, [%4];"
                 : "=r"(r[0]), "=r"(r[1]), "=r"(r[2]), "=r"(r[3]) : "r"(addr));
}

__device__ __forceinline__ void mma16816(float* c, const uint32_t* a, uint32_t b0, uint32_t b1) {
    asm volatile("mma.sync.aligned.m16n8k16.row.col.f32.f16.f16.f32 "
                 "{%0,%1,%2,%3}, {%4,%5,%6,%7}, {%8,%9}, {%0,%1,%2,%3};"
                 : "+f"(c[0]), "+f"(c[1]), "+f"(c[2]), "+f"(c[3])
                 : "r"(a[0]), "r"(a[1]), "r"(a[2]), "r"(a[3]), "r"(b0), "r"(b1));
}

// =====================================================================
// K1: per-output-row weight absmax -> fc_sf, bias_sf, b_int; reset max
// =====================================================================
__global__ void __launch_bounds__(256) k_stats(const float* __restrict__ W,
                                               const float* __restrict__ b,
                                               const float* __restrict__ asf,
                                               float* __restrict__ out_fc) {
    __shared__ float red[256];
    int o = blockIdx.x;
    int t = threadIdx.x;
    const float4* w4 = reinterpret_cast<const float4*>(W + (size_t)o * K_DIM);
    float am = 0.f;
#pragma unroll
    for (int j = 0; j < 4; j++) {
        float4 v = __ldg(w4 + t + j * 256);
        am = fmaxf(am, fmaxf(fmaxf(fabsf(v.x), fabsf(v.y)), fmaxf(fabsf(v.z), fabsf(v.w))));
    }
    red[t] = am;
    __syncthreads();
    for (int s = 128; s > 0; s >>= 1) {
        if (t < s) red[t] = fmaxf(red[t], red[t + s]);
        __syncthreads();
    }
    if (t == 0) {
        float fc = __fdiv_rn(fmaxf(red[0], 1e-8f), 127.0f);
        float a  = __ldg(asf);
        float bs = __fmul_rn(fc, a);
        g_fc_sf[o]   = fc;
        g_bias_sf[o] = bs;
        g_b_int[o]   = rintf(__fdiv_rn(__ldg(b + o), bs));
        out_fc[o]    = fc;
        if (o == 0) g_max_bits = 0u;
    }
}

// =====================================================================
// K2: quantize W -> fp16 w_int, pre-swizzled tile-contiguous layout
//     tile (tn, ks): 256 rows(o) x 64 fp16 (128B/row), SW128 swizzled
// =====================================================================
__global__ void __launch_bounds__(256) k_packw(const float* __restrict__ W) {
    unsigned g = blockIdx.x * 256u + threadIdx.x;
    int o = (int)(g >> 9);
    int k = (int)((g & 511u) << 3);
    float fc = __ldg(&g_fc_sf[o]);
    const float4* w4 = reinterpret_cast<const float4*>(W + (size_t)o * K_DIM + k);
    float4 v0 = __ldg(w4), v1 = __ldg(w4 + 1);
    float vv[8] = {v0.x, v0.y, v0.z, v0.w, v1.x, v1.y, v1.z, v1.w};
    unsigned us[8];
#pragma unroll
    for (int i = 0; i < 8; i++) {
        float r = fminf(fmaxf(rintf(__fdiv_rn(vv[i], fc)), -128.f), 127.f);
        us[i] = (unsigned)__half_as_ushort(__float2half_rn(r));
    }
    uint4 pk;
    pk.x = us[0] | (us[1] << 16);
    pk.y = us[2] | (us[3] << 16);
    pk.z = us[4] | (us[5] << 16);
    pk.w = us[6] | (us[7] << 16);
    int tn = o >> 8, o_in = o & 255, ks = k >> 6, k_in = k & 63;
    unsigned off = (unsigned)(o_in * 128 + k_in * 2);
    off ^= (off >> 3) & 0x70;
    *reinterpret_cast<uint4*>(g_w_packed + (((size_t)(tn * KSTAGES + ks)) << 15) + off) = pk;
}

// =====================================================================
// K3: x_int = x/act_sf, split into fp16 hi/lo limbs, pre-swizzled tiles
//     tile (tm, ks): 128 rows(b) x 64 fp16 (128B/row), SW128 swizzled
// =====================================================================
__global__ void __launch_bounds__(256) k_packx(const float* __restrict__ X,
                                               const float* __restrict__ asf) {
    unsigned g = blockIdx.x * 256u + threadIdx.x;
    int bb = (int)(g >> 9);
    int k  = (int)((g & 511u) << 3);
    float a = __ldg(asf);
    const float4* x4 = reinterpret_cast<const float4*>(X + (size_t)bb * K_DIM + k);
    float4 v0 = __ldg(x4), v1 = __ldg(x4 + 1);
    float vv[8] = {v0.x, v0.y, v0.z, v0.w, v1.x, v1.y, v1.z, v1.w};
    unsigned uh[8], ul[8];
#pragma unroll
    for (int i = 0; i < 8; i++) {
        float xi = __fdiv_rn(vv[i], a);
        __half hh = __float2half_rn(xi);
        float lo = xi - __half2float(hh);   // exact (Sterbenz)
        uh[i] = (unsigned)__half_as_ushort(hh);
        ul[i] = (unsigned)__half_as_ushort(__float2half_rn(lo));
    }
    uint4 ph, pl;
    ph.x = uh[0] | (uh[1] << 16); ph.y = uh[2] | (uh[3] << 16);
    ph.z = uh[4] | (uh[5] << 16); ph.w = uh[6] | (uh[7] << 16);
    pl.x = ul[0] | (ul[1] << 16); pl.y = ul[2] | (ul[3] << 16);
    pl.z = ul[4] | (ul[5] << 16); pl.w = ul[6] | (ul[7] << 16);
    int tm = bb >> 7, m_in = bb & 127, ks = k >> 6, k_in = k & 63;
    unsigned off = (unsigned)(m_in * 128 + k_in * 2);
    off ^= (off >> 3) & 0x70;
    size_t tb = ((size_t)(tm * KSTAGES + ks)) << 14;
    *reinterpret_cast<uint4*>(g_x_hi + tb + off) = ph;
    *reinterpret_cast<uint4*>(g_x_lo + tb + off) = pl;
}

// =====================================================================
// K4: mma.sync fp16 GEMM, 128x256 CTA tile, 2 limbs, fp32 accum.
//     cp.async.bulk 3-stage pipeline from pre-swizzled scratch.
//     Epilogue: (acc + b_int)*bias_sf, ReLU, row-major store + global max.
// =====================================================================
__global__ void __launch_bounds__(256, 1) k_gemm() {
    extern __shared__ unsigned char smem_raw[];
    __shared__ __align__(8) uint64_t mbar_store[NSTAGE];
    uint32_t base = (smem_u32(smem_raw) + 1023u) & ~1023u;
    uint32_t mb = smem_u32(mbar_store);

    int tid = threadIdx.x;
    int lane = tid & 31;
    int w = tid >> 5;
    int wm = w & 3;        // 4 warps along M (32 rows each)
    int wn = w >> 2;       // 2 warps along N (128 cols each)
    int bid = blockIdx.x;
    int tn = bid & 15;
    int tm = bid >> 4;

    if (tid == 0) {
#pragma unroll
        for (int s = 0; s < NSTAGE; s++) MBAR_INIT(mb + s * 8, 1);
    }
    __syncthreads();

    const unsigned char* sAh = g_x_hi + (size_t)(tm * KSTAGES) * A_TILE_BYTES;
    const unsigned char* sAl = g_x_lo + (size_t)(tm * KSTAGES) * A_TILE_BYTES;
    const unsigned char* sB  = g_w_packed + (size_t)(tn * KSTAGES) * B_TILE_BYTES;

    // prologue: fill all 3 stages
    if (tid == 0) {
#pragma unroll
        for (int s = 0; s < NSTAGE; s++) {
            uint32_t st = base + s * STG_BYTES;
            uint32_t fb = mb + s * 8;
            MBAR_EXPECT_TX(fb, STG_BYTES);
            BULK_G2S(st,                 sAh + (size_t)s * A_TILE_BYTES, A_TILE_BYTES, fb);
            BULK_G2S(st + A_TILE_BYTES,  sAl + (size_t)s * A_TILE_BYTES, A_TILE_BYTES, fb);
            BULK_G2S(st + 2 * A_TILE_BYTES, sB + (size_t)s * B_TILE_BYTES, B_TILE_BYTES, fb);
        }
    }

    float acc[2][16][4];
#pragma unroll
    for (int i = 0; i < 2; i++)
#pragma unroll
        for (int j = 0; j < 16; j++)
#pragma unroll
            for (int r = 0; r < 4; r++) acc[i][j][r] = 0.f;

    int arow = lane & 15;
    int agr16 = (lane >> 4) << 4;   // 0 or 16 bytes

    for (int ks = 0; ks < KSTAGES; ks++) {
        int s = ks % NSTAGE;
        int par = (ks / NSTAGE) & 1;
        MBAR_WAIT(mb + s * 8, par);
        uint32_t stA = base + s * STG_BYTES;
        uint32_t stB = stA + 2 * A_TILE_BYTES;
#pragma unroll
        for (int kk = 0; kk < 4; kk++) {
            uint32_t afr[2][2][4];   // [limb][mf][4]
#pragma unroll
            for (int mf = 0; mf < 2; mf++) {
                int row = wm * 32 + mf * 16 + arow;
                uint32_t off = (uint32_t)(row * 128 + kk * 32 + agr16);
                off ^= (off >> 3) & 0x70;
                ldsm_x4(afr[0][mf], stA + off);
                ldsm_x4(afr[1][mf], stA + A_TILE_BYTES + off);
            }
#pragma unroll
            for (int np = 0; np < 8; np++) {
                int row = wn * 128 + np * 16 + arow;
                uint32_t off = (uint32_t)(row * 128 + kk * 32 + agr16);
                off ^= (off >> 3) & 0x70;
                uint32_t bfr[4];
                ldsm_x4(bfr, stB + off);
#pragma unroll
                for (int mf = 0; mf < 2; mf++) {
#pragma unroll
                    for (int l = 0; l < 2; l++) {
                        mma16816(acc[mf][2 * np],     afr[l][mf], bfr[0], bfr[2]);
                        mma16816(acc[mf][2 * np + 1], afr[l][mf], bfr[1], bfr[3]);
                    }
                }
            }
        }
        __syncthreads();
        if (ks + NSTAGE < KSTAGES && tid == 0) {
            int ns = ks + NSTAGE;
            uint32_t st = base + s * STG_BYTES;
            uint32_t fb = mb + s * 8;
            MBAR_EXPECT_TX(fb, STG_BYTES);
            BULK_G2S(st,                 sAh + (size_t)ns * A_TILE_BYTES, A_TILE_BYTES, fb);
            BULK_G2S(st + A_TILE_BYTES,  sAl + (size_t)ns * A_TILE_BYTES, A_TILE_BYTES, fb);
            BULK_G2S(st + 2 * A_TILE_BYTES, sB + (size_t)ns * B_TILE_BYTES, B_TILE_BYTES, fb);
        }
    }

    // -------- epilogue --------
    float lmax = 0.f;
    int orow = lane >> 2;
    int ocol = (lane & 3) * 2;
    int obase = tn * TN + wn * 128;
    size_t mbase = (size_t)tm * TM + wm * 32 + orow;
#pragma unroll
    for (int mf = 0; mf < 2; mf++) {
        size_t m0 = mbase + mf * 16;
#pragma unroll
        for (int nf = 0; nf < 16; nf++) {
            int o = obase + nf * 8 + ocol;
            float bs0 = __ldg(&g_bias_sf[o]);
            float bs1 = __ldg(&g_bias_sf[o + 1]);
            float bi0 = __ldg(&g_b_int[o]);
            float bi1 = __ldg(&g_b_int[o + 1]);
            float v0 = fmaxf((acc[mf][nf][0] + bi0) * bs0, 0.f);
            float v1 = fmaxf((acc[mf][nf][1] + bi1) * bs1, 0.f);
            float v2 = fmaxf((acc[mf][nf][2] + bi0) * bs0, 0.f);
            float v3 = fmaxf((acc[mf][nf][3] + bi1) * bs1, 0.f);
            lmax = fmaxf(lmax, fmaxf(fmaxf(v0, v1), fmaxf(v2, v3)));
            float2 p0 = make_float2(v0, v1);
            float2 p1 = make_float2(v2, v3);
            *reinterpret_cast<float2*>(&g_out[m0 * N_DIM + o]) = p0;
            *reinterpret_cast<float2*>(&g_out[(m0 + 8) * N_DIM + o]) = p1;
        }
    }
#pragma unroll
    for (int off = 16; off > 0; off >>= 1)
        lmax = fmaxf(lmax, __shfl_xor_sync(0xFFFFFFFFu, lmax, off));
    if (lane == 0) atomicMax(&g_max_bits, __float_as_uint(lmax));
}

// =====================================================================
// K5: act_sf_new scalar
// =====================================================================
__global__ void k_sf(float* __restrict__ out_tail) {
    float xm = __uint_as_float(g_max_bits);
    float sf = __fdiv_rn(fmaxf(xm, 1e-8f), 255.0f);
    g_act_sf = sf;
    out_tail[0] = sf;
}

// =====================================================================
// K6: elementwise requantize (zp = 0 since min is 0 post-ReLU)
// =====================================================================
__global__ void __launch_bounds__(256) k_requant(float* __restrict__ out) {
    size_t i = ((size_t)blockIdx.x * 256 + threadIdx.x) * 4;
    float sf = g_act_sf;
    float4 v = *reinterpret_cast<const float4*>(&g_out[i]);
    float4 r;
    r.x = fminf(fmaxf(rintf(__fdiv_rn(v.x, sf)), 0.f), 255.f) * sf;
    r.y = fminf(fmaxf(rintf(__fdiv_rn(v.y, sf)), 0.f), 255.f) * sf;
    r.z = fminf(fmaxf(rintf(__fdiv_rn(v.z, sf)), 0.f), 255.f) * sf;
    r.w = fminf(fmaxf(rintf(__fdiv_rn(v.w, sf)), 0.f), 255.f) * sf;
    *reinterpret_cast<float4*>(&out[i]) = r;
}

// =====================================================================
// launch
// =====================================================================
extern "C" void kernel_launch(void* const* d_in, const int* in_sizes, int n_in,
                              void* d_out, int out_size) {
    const float* x = nullptr;
    const float* asf = nullptr;
    const float* W = nullptr;
    const float* b = nullptr;
    for (int i = 0; i < n_in; i++) {
        long s = in_sizes[i];
        if (s == (long)B_ROWS * K_DIM)      x   = (const float*)d_in[i];
        else if (s == (long)N_DIM * K_DIM)  W   = (const float*)d_in[i];
        else if (s == N_DIM)                b   = (const float*)d_in[i];
        else if (s == 1)                    asf = (const float*)d_in[i];
    }
    if (!x)   x   = (const float*)d_in[0];
    if (!asf) asf = (const float*)d_in[1];
    if (!W)   W   = (const float*)d_in[2];
    if (!b)   b   = (const float*)d_in[3];

    float* out = (float*)d_out;
    float* out_fc   = out + (size_t)B_ROWS * N_DIM;
    float* out_tail = out_fc + N_DIM;

    cudaFuncSetAttribute(k_gemm, cudaFuncAttributeMaxDynamicSharedMemorySize, SMEM_DYN);

    k_stats<<<N_DIM, 256>>>(W, b, asf, out_fc);
    k_packw<<<(N_DIM * (K_DIM / 8)) / 256, 256>>>(W);
    k_packx<<<(B_ROWS * (K_DIM / 8)) / 256, 256>>>(x, asf);
    k_gemm<<<(B_ROWS / TM) * (N_DIM / TN), 256, SMEM_DYN>>>();
    k_sf<<<1, 1>>>(out_tail);
    k_requant<<<(B_ROWS * N_DIM) / (256 * 4), 256>>>(out);
}